// round 12
// baseline (speedup 1.0000x reference)
#include <cuda_runtime.h>

// 1024 x 1024 raster, fixed topology (links are the standard 4-neighbor raster
// links generated by _raster_links; perimeter nodes are status=1 boundaries).
#define NROWS 1024
#define NCOLS 1024
#define NN (NROWS * NCOLS)

#define RHOW_G     9810.0f        // RHO_W * GRAV
#define SEC_PER_A  31556926.0f
#define FLOW_COEFF 0.0405f

// Scratch (static device globals; no allocation at runtime).
__device__ float  g_phi[NN];
__device__ float  g_runoff[NN];
__device__ float  g_invd[NN];    // core[i] && total_drop>0 ? 1/total_drop : 0
__device__ float4 g_w[NN];       // incoming weights from (W, E, N, S) neighbors
__device__ float  g_q[2][NN];    // ping-pong discharge buffers

__global__ void prep_kernel(const float* __restrict__ melt,
                            const float* __restrict__ bed,
                            const float* __restrict__ wp,
                            const float* __restrict__ area) {
    int i = blockIdx.x * blockDim.x + threadIdx.x;
    if (i >= NN) return;
    g_phi[i]    = RHOW_G * bed[i] + wp[i];
    g_runoff[i] = melt[i] * area[i] / SEC_PER_A;
}

// total outgoing positive potential drop per node -> gated reciprocal
__global__ void invd_kernel(const int* __restrict__ status) {
    int i = blockIdx.x * blockDim.x + threadIdx.x;
    if (i >= NN) return;
    float v = 0.0f;
    if (status[i] == 0) {
        int c = i & (NCOLS - 1);
        int r = i >> 10;
        float p = g_phi[i];
        float t = 0.0f;
        if (c > 0)         t += fmaxf(p - g_phi[i - 1],     0.0f);
        if (c < NCOLS - 1) t += fmaxf(p - g_phi[i + 1],     0.0f);
        if (r > 0)         t += fmaxf(p - g_phi[i - NCOLS], 0.0f);
        if (r < NROWS - 1) t += fmaxf(p - g_phi[i + NCOLS], 0.0f);
        v = (t > 0.0f) ? (1.0f / t) : 0.0f;
    }
    g_invd[i] = v;
}

// Incoming weight into node i from each neighbor j:
//   w = max(phi[j] - phi[i], 0) * invd[j]
// (invd[j] already encodes core[j] and the s_safe gating)
__global__ void weights_kernel() {
    int i = blockIdx.x * blockDim.x + threadIdx.x;
    if (i >= NN) return;
    int c = i & (NCOLS - 1);
    int r = i >> 10;
    float p = g_phi[i];
    float4 w = make_float4(0.f, 0.f, 0.f, 0.f);
    if (c > 0)         { int j = i - 1;     w.x = fmaxf(g_phi[j] - p, 0.0f) * g_invd[j]; }
    if (c < NCOLS - 1) { int j = i + 1;     w.y = fmaxf(g_phi[j] - p, 0.0f) * g_invd[j]; }
    if (r > 0)         { int j = i - NCOLS; w.z = fmaxf(g_phi[j] - p, 0.0f) * g_invd[j]; }
    if (r < NROWS - 1) { int j = i + NCOLS; w.w = fmaxf(g_phi[j] - p, 0.0f) * g_invd[j]; }
    g_w[i] = w;
}

__device__ __forceinline__ float stencil_node(int i, const float* __restrict__ qin) {
    float4 w = g_w[i];
    float acc = g_runoff[i];
    // Weights are exactly 0 for nonexistent neighbors, so clamped indices are
    // safe (values are finite, contribution is 0*finite = 0).
    int iW = (i - 1     >= 0) ? i - 1     : i;
    int iE = (i + 1     < NN) ? i + 1     : i;
    int iN = (i - NCOLS >= 0) ? i - NCOLS : i;
    int iS = (i + NCOLS < NN) ? i + NCOLS : i;
    acc = fmaf(w.x, __ldg(&qin[iW]), acc);
    acc = fmaf(w.y, __ldg(&qin[iE]), acc);
    acc = fmaf(w.z, __ldg(&qin[iN]), acc);
    acc = fmaf(w.w, __ldg(&qin[iS]), acc);
    return acc;
}

// One Jacobi iteration: q_out = runoff + W^T q_in
// in_sel: -1 -> read g_runoff (q0), else g_q[in_sel]
__global__ void stencil_kernel(int in_sel, int out_sel) {
    int i = blockIdx.x * blockDim.x + threadIdx.x;
    if (i >= NN) return;
    const float* qin = (in_sel < 0) ? g_runoff : g_q[in_sel];
    g_q[out_sel][i] = stencil_node(i, qin);
}

// Final iteration fused with the hydraulic-gradient epilogue.
__global__ void final_kernel(int in_sel,
                             const float* __restrict__ conduit,
                             const int*   __restrict__ status,
                             float* __restrict__ out) {
    int i = blockIdx.x * blockDim.x + threadIdx.x;
    if (i >= NN) return;
    const float* qin = (in_sel < 0) ? g_runoff : g_q[in_sel];
    float q = stencil_node(i, qin);
    float g = q * FLOW_COEFF * powf(conduit[i], 1.25f);
    out[i] = (status[i] == 0) ? g * g : 0.0f;
}

extern "C" void kernel_launch(void* const* d_in, const int* in_sizes, int n_in,
                              void* d_out, int out_size) {
    const float* melt   = (const float*)d_in[0];
    const float* bed    = (const float*)d_in[1];
    const float* wp     = (const float*)d_in[2];
    const float* area   = (const float*)d_in[3];
    const float* cond   = (const float*)d_in[4];
    const int*   status = (const int*)  d_in[5];
    float* out = (float*)d_out;

    const int BLK = 256;
    const int GRD = NN / BLK;

    prep_kernel<<<GRD, BLK>>>(melt, bed, wp, area);
    invd_kernel<<<GRD, BLK>>>(status);
    weights_kernel<<<GRD, BLK>>>();

    // 32 stencil applications total: 1 (from runoff) + 30 ping-pong + 1 fused final
    stencil_kernel<<<GRD, BLK>>>(-1, 0);
    int cur = 0;
    for (int it = 2; it <= 31; ++it) {
        stencil_kernel<<<GRD, BLK>>>(cur, cur ^ 1);
        cur ^= 1;
    }
    final_kernel<<<GRD, BLK>>>(cur, cond, status, out);
}

// round 13
// speedup vs baseline: 1.5484x; 1.5484x over previous
#include <cuda_runtime.h>

// 1024 x 1024 raster, fixed topology (4-neighbor raster links; perimeter
// nodes are status=1 boundaries).
#define NROWS 1024
#define NCOLS 1024
#define NN (NROWS * NCOLS)

#define RHOW_G     9810.0f        // RHO_W * GRAV
#define SEC_PER_A  31556926.0f
#define FLOW_COEFF 0.0405f

// Temporal-fusion tiling: 4 Jacobi steps per kernel launch.
#define KSTEPS 4
#define TILE   32                 // output tile edge
#define HALO   KSTEPS
#define REG    (TILE + 2 * HALO)  // 40: staged region edge
#define RCELLS (REG * REG)        // 1600
#define TPB    256
#define CPT    ((RCELLS + TPB - 1) / TPB)  // 7 cells per thread (fixed ownership)

// Scratch (static device globals; no allocation at runtime).
__device__ float  g_phi[NN];
__device__ float  g_runoff[NN];
__device__ float  g_invd[NN];    // core[i] && total_drop>0 ? 1/total_drop : 0
__device__ float4 g_w[NN];       // incoming weights from (W, E, N, S) neighbors
__device__ float  g_q[2][NN];    // ping-pong discharge buffers (chunk granularity)

__global__ void prep_kernel(const float* __restrict__ melt,
                            const float* __restrict__ bed,
                            const float* __restrict__ wp,
                            const float* __restrict__ area) {
    int i = blockIdx.x * blockDim.x + threadIdx.x;
    if (i >= NN) return;
    g_phi[i]    = RHOW_G * bed[i] + wp[i];
    g_runoff[i] = melt[i] * area[i] / SEC_PER_A;
}

// total outgoing positive potential drop per node -> gated reciprocal
__global__ void invd_kernel(const int* __restrict__ status) {
    int i = blockIdx.x * blockDim.x + threadIdx.x;
    if (i >= NN) return;
    float v = 0.0f;
    if (status[i] == 0) {
        int c = i & (NCOLS - 1);
        int r = i >> 10;
        float p = g_phi[i];
        float t = 0.0f;
        if (c > 0)         t += fmaxf(p - g_phi[i - 1],     0.0f);
        if (c < NCOLS - 1) t += fmaxf(p - g_phi[i + 1],     0.0f);
        if (r > 0)         t += fmaxf(p - g_phi[i - NCOLS], 0.0f);
        if (r < NROWS - 1) t += fmaxf(p - g_phi[i + NCOLS], 0.0f);
        v = (t > 0.0f) ? (1.0f / t) : 0.0f;
    }
    g_invd[i] = v;
}

// Incoming weight into node i from each neighbor j:
//   w = max(phi[j] - phi[i], 0) * invd[j]
// (invd[j] already encodes core[j] and the s_safe gating)
__global__ void weights_kernel() {
    int i = blockIdx.x * blockDim.x + threadIdx.x;
    if (i >= NN) return;
    int c = i & (NCOLS - 1);
    int r = i >> 10;
    float p = g_phi[i];
    float4 w = make_float4(0.f, 0.f, 0.f, 0.f);
    if (c > 0)         { int j = i - 1;     w.x = fmaxf(g_phi[j] - p, 0.0f) * g_invd[j]; }
    if (c < NCOLS - 1) { int j = i + 1;     w.y = fmaxf(g_phi[j] - p, 0.0f) * g_invd[j]; }
    if (r > 0)         { int j = i - NCOLS; w.z = fmaxf(g_phi[j] - p, 0.0f) * g_invd[j]; }
    if (r < NROWS - 1) { int j = i + NCOLS; w.w = fmaxf(g_phi[j] - p, 0.0f) * g_invd[j]; }
    g_w[i] = w;
}

// Fused temporal-block kernel: KSTEPS Jacobi iterations per launch.
//   q_out = (runoff + W^T q)^(KSTEPS applied)
// Each block stages a REGxREG region of q in smem (ping/pong), keeps the
// iteration-invariant weights and runoff in registers (fixed thread->cell
// ownership), and writes only the TILE x TILE core.
// If FINAL, the last step is fused with the hydraulic-gradient epilogue.
template <bool FINAL>
__global__ void __launch_bounds__(TPB)
fused_stencil(const float* __restrict__ qin,
              float* __restrict__ qout,
              const float* __restrict__ conduit,
              const int*   __restrict__ status) {
    __shared__ float sq[2][RCELLS];

    const int bx  = blockIdx.x & (NCOLS / TILE - 1);
    const int by  = blockIdx.x >> 5;           // NCOLS/TILE == 32
    const int gx0 = bx * TILE - HALO;
    const int gy0 = by * TILE - HALO;
    const int tid = threadIdx.x;

    float4 wreg[CPT];
    float  rreg[CPT];
    int    lxr[CPT], lyr[CPT];

    // Stage region: q -> smem, w/runoff -> registers. Out-of-raster halo
    // cells get q=0, w=0, runoff=0 (their values are never used with
    // nonzero weight: boundary-facing weights are exactly 0).
#pragma unroll
    for (int k = 0; k < CPT; k++) {
        int c = tid + k * TPB;
        if (c >= RCELLS) { lxr[k] = -1; continue; }
        int y = c / REG, x = c - y * REG;
        lxr[k] = x; lyr[k] = y;
        int gx = gx0 + x, gy = gy0 + y;
        bool inr = (gx >= 0) & (gx < NCOLS) & (gy >= 0) & (gy < NROWS);
        int gi = gy * NCOLS + gx;
        float q0 = 0.0f;
        float4 w = make_float4(0.f, 0.f, 0.f, 0.f);
        float rn = 0.0f;
        if (inr) {
            q0 = __ldg(&qin[gi]);
            w  = g_w[gi];
            rn = g_runoff[gi];
        }
        wreg[k] = w;
        rreg[k] = rn;
        sq[0][c] = q0;
    }
    __syncthreads();

    // KSTEPS Jacobi sweeps over shrinking valid regions.
    int ping = 0;
#pragma unroll
    for (int s = 1; s <= KSTEPS; s++) {
#pragma unroll
        for (int k = 0; k < CPT; k++) {
            int x = lxr[k], y = lyr[k];
            if (x < s || x >= REG - s || y < s || y >= REG - s) continue;
            int c = y * REG + x;
            float acc = rreg[k];
            acc = fmaf(wreg[k].x, sq[ping][c - 1],   acc);
            acc = fmaf(wreg[k].y, sq[ping][c + 1],   acc);
            acc = fmaf(wreg[k].z, sq[ping][c - REG], acc);
            acc = fmaf(wreg[k].w, sq[ping][c + REG], acc);
            sq[ping ^ 1][c] = acc;
        }
        __syncthreads();
        ping ^= 1;
    }

    // Write the TILE x TILE core.
#pragma unroll
    for (int k = 0; k < CPT; k++) {
        int x = lxr[k], y = lyr[k];
        if (x < HALO || x >= REG - HALO || y < HALO || y >= REG - HALO) continue;
        int gi = (gy0 + y) * NCOLS + (gx0 + x);
        float q = sq[ping][y * REG + x];
        if (FINAL) {
            float g = q * FLOW_COEFF * powf(conduit[gi], 1.25f);
            qout[gi] = (status[gi] == 0) ? g * g : 0.0f;
        } else {
            qout[gi] = q;
        }
    }
}

extern "C" void kernel_launch(void* const* d_in, const int* in_sizes, int n_in,
                              void* d_out, int out_size) {
    const float* melt   = (const float*)d_in[0];
    const float* bed    = (const float*)d_in[1];
    const float* wp     = (const float*)d_in[2];
    const float* area   = (const float*)d_in[3];
    const float* cond   = (const float*)d_in[4];
    const int*   status = (const int*)  d_in[5];
    float* out = (float*)d_out;

    const int BLK = 256;
    const int GRD = NN / BLK;

    prep_kernel<<<GRD, BLK>>>(melt, bed, wp, area);
    invd_kernel<<<GRD, BLK>>>(status);
    weights_kernel<<<GRD, BLK>>>();

    // Resolve the __device__ globals to raw pointers once (host-side; these
    // driver queries are graph-capture-safe since they are not stream ops).
    static float* q0 = nullptr;
    static float* q1 = nullptr;
    static float* rn = nullptr;
    if (!q0) {
        void* p;
        cudaGetSymbolAddress(&p, g_q);      q0 = (float*)p;
        q1 = q0 + NN;
        cudaGetSymbolAddress(&p, g_runoff); rn = (float*)p;
    }

    const int FGRD = (NROWS / TILE) * (NCOLS / TILE);  // 1024 blocks
    const int NCHUNKS = 32 / KSTEPS;                   // 8 launches, 4 steps each

    // chunk 1: runoff -> q0; chunks 2..7 ping-pong; chunk 8 fused epilogue.
    fused_stencil<false><<<FGRD, TPB>>>(rn, q0, nullptr, nullptr);
    const float* cur = q0;
    float* nxt = q1;
    for (int ch = 2; ch <= NCHUNKS - 1; ++ch) {
        fused_stencil<false><<<FGRD, TPB>>>(cur, nxt, nullptr, nullptr);
        const float* t = cur; cur = nxt; nxt = (float*)t;
    }
    fused_stencil<true><<<FGRD, TPB>>>(cur, out, cond, status);
}

// round 14
// speedup vs baseline: 1.5527x; 1.0028x over previous
#include <cuda_runtime.h>

// 1024 x 1024 raster, fixed topology (4-neighbor raster links; perimeter
// nodes are status=1 boundaries).
#define NROWS 1024
#define NCOLS 1024
#define NN (NROWS * NCOLS)

#define RHOW_G     9810.0f        // RHO_W * GRAV
#define SEC_PER_A  31556926.0f
#define FLOW_COEFF 0.0405f

// Temporal-fusion tiling: 4 Jacobi steps per kernel launch.
#define KSTEPS 4
#define TILE   32                 // output tile edge
#define HALO   KSTEPS
#define REG    (TILE + 2 * HALO)  // 40: staged region edge
#define RCELLS (REG * REG)        // 1600
#define TPB    256
#define CPT    ((RCELLS + TPB - 1) / TPB)  // 7 cells per thread (fixed ownership)

// Scratch (static device globals; no allocation at runtime).
__device__ float  g_phi[NN];
__device__ float  g_runoff[NN];
__device__ float  g_invd[NN];    // core[i] && total_drop>0 ? 1/total_drop : 0
__device__ float4 g_w[NN];       // incoming weights from (W, E, N, S) neighbors
__device__ float  g_q[2][NN];    // ping-pong discharge buffers (chunk granularity)

__global__ void prep_kernel(const float* __restrict__ melt,
                            const float* __restrict__ bed,
                            const float* __restrict__ wp,
                            const float* __restrict__ area) {
    int i = blockIdx.x * blockDim.x + threadIdx.x;
    if (i >= NN) return;
    g_phi[i]    = RHOW_G * bed[i] + wp[i];
    g_runoff[i] = melt[i] * area[i] / SEC_PER_A;
}

// total outgoing positive potential drop per node -> gated reciprocal
__global__ void invd_kernel(const int* __restrict__ status) {
    int i = blockIdx.x * blockDim.x + threadIdx.x;
    if (i >= NN) return;
    float v = 0.0f;
    if (status[i] == 0) {
        int c = i & (NCOLS - 1);
        int r = i >> 10;
        float p = g_phi[i];
        float t = 0.0f;
        if (c > 0)         t += fmaxf(p - g_phi[i - 1],     0.0f);
        if (c < NCOLS - 1) t += fmaxf(p - g_phi[i + 1],     0.0f);
        if (r > 0)         t += fmaxf(p - g_phi[i - NCOLS], 0.0f);
        if (r < NROWS - 1) t += fmaxf(p - g_phi[i + NCOLS], 0.0f);
        v = (t > 0.0f) ? (1.0f / t) : 0.0f;
    }
    g_invd[i] = v;
}

// Incoming weight into node i from each neighbor j:
//   w = max(phi[j] - phi[i], 0) * invd[j]
// (invd[j] already encodes core[j] and the s_safe gating)
__global__ void weights_kernel() {
    int i = blockIdx.x * blockDim.x + threadIdx.x;
    if (i >= NN) return;
    int c = i & (NCOLS - 1);
    int r = i >> 10;
    float p = g_phi[i];
    float4 w = make_float4(0.f, 0.f, 0.f, 0.f);
    if (c > 0)         { int j = i - 1;     w.x = fmaxf(g_phi[j] - p, 0.0f) * g_invd[j]; }
    if (c < NCOLS - 1) { int j = i + 1;     w.y = fmaxf(g_phi[j] - p, 0.0f) * g_invd[j]; }
    if (r > 0)         { int j = i - NCOLS; w.z = fmaxf(g_phi[j] - p, 0.0f) * g_invd[j]; }
    if (r < NROWS - 1) { int j = i + NCOLS; w.w = fmaxf(g_phi[j] - p, 0.0f) * g_invd[j]; }
    g_w[i] = w;
}

// Fused temporal-block kernel: KSTEPS Jacobi iterations per launch.
//   q_out = (runoff + W^T q)^(KSTEPS applied)
// Each block stages a REGxREG region of q in smem (ping/pong), keeps the
// iteration-invariant weights and runoff in registers (fixed thread->cell
// ownership), and writes only the TILE x TILE core.
// If FINAL, the last step is fused with the hydraulic-gradient epilogue.
template <bool FINAL>
__global__ void __launch_bounds__(TPB)
fused_stencil(const float* __restrict__ qin,
              float* __restrict__ qout,
              const float* __restrict__ conduit,
              const int*   __restrict__ status) {
    __shared__ float sq[2][RCELLS];

    const int bx  = blockIdx.x & (NCOLS / TILE - 1);
    const int by  = blockIdx.x >> 5;           // NCOLS/TILE == 32
    const int gx0 = bx * TILE - HALO;
    const int gy0 = by * TILE - HALO;
    const int tid = threadIdx.x;

    float4 wreg[CPT];
    float  rreg[CPT];
    int    lxr[CPT], lyr[CPT];

    // Stage region: q -> smem, w/runoff -> registers. Out-of-raster halo
    // cells get q=0, w=0, runoff=0 (their values are never used with
    // nonzero weight: boundary-facing weights are exactly 0).
#pragma unroll
    for (int k = 0; k < CPT; k++) {
        int c = tid + k * TPB;
        if (c >= RCELLS) { lxr[k] = -1; continue; }
        int y = c / REG, x = c - y * REG;
        lxr[k] = x; lyr[k] = y;
        int gx = gx0 + x, gy = gy0 + y;
        bool inr = (gx >= 0) & (gx < NCOLS) & (gy >= 0) & (gy < NROWS);
        int gi = gy * NCOLS + gx;
        float q0 = 0.0f;
        float4 w = make_float4(0.f, 0.f, 0.f, 0.f);
        float rn = 0.0f;
        if (inr) {
            q0 = __ldg(&qin[gi]);
            w  = g_w[gi];
            rn = g_runoff[gi];
        }
        wreg[k] = w;
        rreg[k] = rn;
        sq[0][c] = q0;
    }
    __syncthreads();

    // KSTEPS Jacobi sweeps over shrinking valid regions.
    int ping = 0;
#pragma unroll
    for (int s = 1; s <= KSTEPS; s++) {
#pragma unroll
        for (int k = 0; k < CPT; k++) {
            int x = lxr[k], y = lyr[k];
            if (x < s || x >= REG - s || y < s || y >= REG - s) continue;
            int c = y * REG + x;
            float acc = rreg[k];
            acc = fmaf(wreg[k].x, sq[ping][c - 1],   acc);
            acc = fmaf(wreg[k].y, sq[ping][c + 1],   acc);
            acc = fmaf(wreg[k].z, sq[ping][c - REG], acc);
            acc = fmaf(wreg[k].w, sq[ping][c + REG], acc);
            sq[ping ^ 1][c] = acc;
        }
        __syncthreads();
        ping ^= 1;
    }

    // Write the TILE x TILE core.
#pragma unroll
    for (int k = 0; k < CPT; k++) {
        int x = lxr[k], y = lyr[k];
        if (x < HALO || x >= REG - HALO || y < HALO || y >= REG - HALO) continue;
        int gi = (gy0 + y) * NCOLS + (gx0 + x);
        float q = sq[ping][y * REG + x];
        if (FINAL) {
            float g = q * FLOW_COEFF * powf(conduit[gi], 1.25f);
            qout[gi] = (status[gi] == 0) ? g * g : 0.0f;
        } else {
            qout[gi] = q;
        }
    }
}

extern "C" void kernel_launch(void* const* d_in, const int* in_sizes, int n_in,
                              void* d_out, int out_size) {
    const float* melt   = (const float*)d_in[0];
    const float* bed    = (const float*)d_in[1];
    const float* wp     = (const float*)d_in[2];
    const float* area   = (const float*)d_in[3];
    const float* cond   = (const float*)d_in[4];
    const int*   status = (const int*)  d_in[5];
    float* out = (float*)d_out;

    const int BLK = 256;
    const int GRD = NN / BLK;

    prep_kernel<<<GRD, BLK>>>(melt, bed, wp, area);
    invd_kernel<<<GRD, BLK>>>(status);
    weights_kernel<<<GRD, BLK>>>();

    // Resolve the __device__ globals to raw pointers once (host-side; these
    // driver queries are graph-capture-safe since they are not stream ops).
    static float* q0 = nullptr;
    static float* q1 = nullptr;
    static float* rn = nullptr;
    if (!q0) {
        void* p;
        cudaGetSymbolAddress(&p, g_q);      q0 = (float*)p;
        q1 = q0 + NN;
        cudaGetSymbolAddress(&p, g_runoff); rn = (float*)p;
    }

    const int FGRD = (NROWS / TILE) * (NCOLS / TILE);  // 1024 blocks
    const int NCHUNKS = 32 / KSTEPS;                   // 8 launches, 4 steps each

    // chunk 1: runoff -> q0; chunks 2..7 ping-pong; chunk 8 fused epilogue.
    fused_stencil<false><<<FGRD, TPB>>>(rn, q0, nullptr, nullptr);
    const float* cur = q0;
    float* nxt = q1;
    for (int ch = 2; ch <= NCHUNKS - 1; ++ch) {
        fused_stencil<false><<<FGRD, TPB>>>(cur, nxt, nullptr, nullptr);
        const float* t = cur; cur = nxt; nxt = (float*)t;
    }
    fused_stencil<true><<<FGRD, TPB>>>(cur, out, cond, status);
}